// round 3
// baseline (speedup 1.0000x reference)
#include <cuda_runtime.h>
#include <math.h>

#define B_   32
#define T_   512
#define H_   1024
#define G4   4096   // 4*H

#define NCTA      128
#define NTHREADS  256

// ---------------------------------------------------------------------------
// Persistent device scratch (no cudaMalloc allowed)
// ---------------------------------------------------------------------------
__device__ float g_xz[(size_t)B_ * T_ * G4];   // [B*T, 4H] input projection
__device__ float g_h[2][B_ * H_];              // double-buffered hidden state
__device__ unsigned g_bar_cnt;
__device__ volatile unsigned g_bar_gen;

// ---------------------------------------------------------------------------
// helpers
// ---------------------------------------------------------------------------
__device__ __forceinline__ unsigned f2tf32(float f) {
    unsigned u;
    asm("cvt.rna.tf32.f32 %0, %1;" : "=r"(u) : "f"(f));
    return u;
}

__device__ __forceinline__ void mma_tf32(float c[4],
                                         unsigned a0, unsigned a1, unsigned a2, unsigned a3,
                                         unsigned b0, unsigned b1) {
    asm volatile(
        "mma.sync.aligned.m16n8k8.row.col.f32.tf32.tf32.f32 "
        "{%0,%1,%2,%3}, {%4,%5,%6,%7}, {%8,%9}, {%0,%1,%2,%3};"
        : "+f"(c[0]), "+f"(c[1]), "+f"(c[2]), "+f"(c[3])
        : "r"(a0), "r"(a1), "r"(a2), "r"(a3), "r"(b0), "r"(b1));
}

__device__ __forceinline__ float sigf(float v) {
    return __fdividef(1.0f, 1.0f + __expf(-v));
}
__device__ __forceinline__ float tanh_fast(float v) {
    return __fdividef(2.0f, 1.0f + __expf(-2.0f * v)) - 1.0f;
}

// ---------------------------------------------------------------------------
// Kernel 0: zero h[0], reset barrier
// ---------------------------------------------------------------------------
__global__ void init_state() {
    int i = blockIdx.x * blockDim.x + threadIdx.x;
    if (i < B_ * H_) g_h[0][i] = 0.0f;
    if (i == 0) { g_bar_cnt = 0; g_bar_gen = 0; }
}

// ---------------------------------------------------------------------------
// Kernel 1: xz = x @ W + b  via tf32 mma.  M=16384, N=4096, K=1024
// CTA tile 64x64, 8 warps 2x4, warp tile 32x16, BK=16.  (unchanged from R2)
// ---------------------------------------------------------------------------
#define AS_STRIDE 20
#define BS_STRIDE 72

__global__ __launch_bounds__(256) void xw_gemm(const float* __restrict__ X,
                                               const float* __restrict__ W,
                                               const float* __restrict__ bias) {
    __shared__ unsigned As[64 * AS_STRIDE];
    __shared__ unsigned Bs[16 * BS_STRIDE];

    const int tid   = threadIdx.x;
    const int lane  = tid & 31;
    const int w     = tid >> 5;
    const int g     = lane >> 2;
    const int tig   = lane & 3;
    const int warpM = w >> 2;
    const int warpN = w & 3;

    const int row0 = blockIdx.y * 64;
    const int col0 = blockIdx.x * 64;

    const int aRow = tid >> 2;
    const int aK   = (tid & 3) * 4;
    const int bK   = tid >> 4;
    const int bN   = (tid & 15) * 4;

    float acc[2][2][4];
#pragma unroll
    for (int i = 0; i < 2; i++)
#pragma unroll
        for (int j = 0; j < 2; j++)
#pragma unroll
            for (int k = 0; k < 4; k++) acc[i][j][k] = 0.0f;

    for (int k0 = 0; k0 < H_; k0 += 16) {
        float4 av = *(const float4*)(X + (size_t)(row0 + aRow) * H_ + k0 + aK);
        As[aRow * AS_STRIDE + aK + 0] = f2tf32(av.x);
        As[aRow * AS_STRIDE + aK + 1] = f2tf32(av.y);
        As[aRow * AS_STRIDE + aK + 2] = f2tf32(av.z);
        As[aRow * AS_STRIDE + aK + 3] = f2tf32(av.w);
        float4 bv = *(const float4*)(W + (size_t)(k0 + bK) * G4 + col0 + bN);
        Bs[bK * BS_STRIDE + bN + 0] = f2tf32(bv.x);
        Bs[bK * BS_STRIDE + bN + 1] = f2tf32(bv.y);
        Bs[bK * BS_STRIDE + bN + 2] = f2tf32(bv.z);
        Bs[bK * BS_STRIDE + bN + 3] = f2tf32(bv.w);
        __syncthreads();

#pragma unroll
        for (int kk = 0; kk < 16; kk += 8) {
            unsigned a[2][4];
#pragma unroll
            for (int mi = 0; mi < 2; mi++) {
                const unsigned* r0 = As + (warpM * 32 + mi * 16 + g) * AS_STRIDE;
                const unsigned* r1 = As + (warpM * 32 + mi * 16 + g + 8) * AS_STRIDE;
                a[mi][0] = r0[kk + tig];
                a[mi][1] = r1[kk + tig];
                a[mi][2] = r0[kk + tig + 4];
                a[mi][3] = r1[kk + tig + 4];
            }
#pragma unroll
            for (int ni = 0; ni < 2; ni++) {
                unsigned b0 = Bs[(kk + tig)     * BS_STRIDE + warpN * 16 + ni * 8 + g];
                unsigned b1 = Bs[(kk + tig + 4) * BS_STRIDE + warpN * 16 + ni * 8 + g];
#pragma unroll
                for (int mi = 0; mi < 2; mi++)
                    mma_tf32(acc[mi][ni], a[mi][0], a[mi][1], a[mi][2], a[mi][3], b0, b1);
            }
        }
        __syncthreads();
    }

#pragma unroll
    for (int mi = 0; mi < 2; mi++) {
#pragma unroll
        for (int ni = 0; ni < 2; ni++) {
            int row = row0 + warpM * 32 + mi * 16 + g;
            int col = col0 + warpN * 16 + ni * 8 + 2 * tig;
            float2 bvv = *(const float2*)(bias + col);
            float2 v0 = make_float2(acc[mi][ni][0] + bvv.x, acc[mi][ni][1] + bvv.y);
            float2 v1 = make_float2(acc[mi][ni][2] + bvv.x, acc[mi][ni][3] + bvv.y);
            *(float2*)(g_xz + (size_t)row * G4 + col)       = v0;
            *(float2*)(g_xz + (size_t)(row + 8) * G4 + col) = v1;
        }
    }
}

// ---------------------------------------------------------------------------
// Kernel 2: persistent LSTM recurrence (restructured for latency).
// 128 CTAs x 256 threads; CTA owns 8 hidden dims (32 z-cols).
// U slice resident in SMEM (tf32, stride 40 -> conflict-free B loads).
// A-fragments (h) loaded DIRECTLY from global via __ldcg as raw fp32 bits
// (tf32 truncation in HW) -> no staging, no cvt, 1 syncthreads per step.
// Warp layout: mi = w>>2 (batch half), ks = w&3 (k quarter of 256).
// ---------------------------------------------------------------------------
#define US_STRIDE  40
#define RED_STRIDE 34                      // 32 + 2 pad
#define US_WORDS   (1024 * US_STRIDE)
#define RED_WORDS  (4 * 32 * RED_STRIDE)
#define SMEM_BYTES ((US_WORDS + RED_WORDS) * 4)

__device__ __forceinline__ void grid_barrier() {
    __syncthreads();
    if (threadIdx.x == 0) {
        unsigned gen = g_bar_gen;
        __threadfence();
        unsigned t = atomicAdd(&g_bar_cnt, 1);
        if (t == NCTA - 1) {
            g_bar_cnt = 0;
            __threadfence();
            g_bar_gen = gen + 1;
        } else {
            while (g_bar_gen == gen) { }
            __threadfence();
        }
    }
    __syncthreads();
}

__global__ __launch_bounds__(NTHREADS, 1) void lstm_persistent(
        const float* __restrict__ U,
        const float* __restrict__ x,
        float* __restrict__ out) {
    extern __shared__ unsigned smem[];
    unsigned* Us = smem;                    // [1024][40]
    float*  redS = (float*)(smem + US_WORDS); // [4][32][34]

    const int tid  = threadIdx.x;
    const int lane = tid & 31;
    const int w    = tid >> 5;
    const int g    = lane >> 2;
    const int tig  = lane & 3;
    const int mi   = w >> 2;     // 0..1 batch half
    const int ks   = w & 3;      // 0..3 k quarter

    const int d0 = blockIdx.x * 8;

    // ---- preload U slice (tf32, RNA) once ----
    for (int idx = tid; idx < 1024 * 32; idx += NTHREADS) {
        int k = idx >> 5;
        int j = idx & 31;
        int gcol = (j >> 3) * H_ + d0 + (j & 7);
        Us[k * US_STRIDE + j] = f2tf32(U[(size_t)k * G4 + gcol]);
    }

    const int eb = tid >> 3;     // batch for gate phase
    const int ed = tid & 7;      // local dim for gate phase
    float c_reg = 0.0f;

    grid_barrier();              // h zeros + U preload visible

    const unsigned* hrow_base0 = (const unsigned*)g_h[0];
    const unsigned* hrow_base1 = (const unsigned*)g_h[1];

    for (int t = 0; t < T_; t++) {
        const unsigned* hprev = (t & 1) ? hrow_base1 : hrow_base0;
        float* hcur           = (t & 1) ? (float*)hrow_base0 : (float*)hrow_base1;

        // ---- prefetch xz + residual x (independent of h) ----
        float zin[4];
#pragma unroll
        for (int gate = 0; gate < 4; gate++)
            zin[gate] = __ldcg(&g_xz[((size_t)eb * T_ + t) * G4 + gate * H_ + d0 + ed]);
        const size_t xi = ((size_t)eb * T_ + t) * H_ + d0 + ed;
        float xres = __ldcg(&x[xi]);

        // ---- z partial: [16 x 32] per warp over k quarter, direct-global A ----
        float acc[4][4];
#pragma unroll
        for (int ni = 0; ni < 4; ni++)
#pragma unroll
            for (int q = 0; q < 4; q++) acc[ni][q] = 0.0f;

        const unsigned* h0 = hprev + (mi * 16 + g) * H_;
        const unsigned* h1 = hprev + (mi * 16 + g + 8) * H_;
        const int kbase = ks * 256;
#pragma unroll 4
        for (int kk = kbase; kk < kbase + 256; kk += 8) {
            unsigned a0 = __ldcg(h0 + kk + tig);
            unsigned a1 = __ldcg(h1 + kk + tig);
            unsigned a2 = __ldcg(h0 + kk + tig + 4);
            unsigned a3 = __ldcg(h1 + kk + tig + 4);
            const unsigned* ub0 = Us + (kk + tig) * US_STRIDE;
            const unsigned* ub1 = Us + (kk + tig + 4) * US_STRIDE;
#pragma unroll
            for (int ni = 0; ni < 4; ni++) {
                mma_tf32(acc[ni], a0, a1, a2, a3, ub0[ni * 8 + g], ub1[ni * 8 + g]);
            }
        }

        // ---- write k-partials (prev step's reads finished before grid barrier) ----
#pragma unroll
        for (int ni = 0; ni < 4; ni++) {
            float* r0 = redS + (ks * 32 + mi * 16 + g)     * RED_STRIDE + ni * 8 + 2 * tig;
            float* r1 = redS + (ks * 32 + mi * 16 + g + 8) * RED_STRIDE + ni * 8 + 2 * tig;
            r0[0] = acc[ni][0];
            r0[1] = acc[ni][1];
            r1[0] = acc[ni][2];
            r1[1] = acc[ni][3];
        }
        __syncthreads();

        // ---- gates + state update + residual tanh ----
        const float* rb = redS + eb * RED_STRIDE + ed;
        float z[4];
#pragma unroll
        for (int gate = 0; gate < 4; gate++) {
            const float* p = rb + gate * 8;
            z[gate] = zin[gate]
                    + p[0]
                    + p[32 * RED_STRIDE]
                    + p[64 * RED_STRIDE]
                    + p[96 * RED_STRIDE];
        }
        float ig = sigf(z[0]);
        float fg = sigf(z[1]);
        float gg = tanh_fast(z[2]);
        float og = sigf(z[3]);

        c_reg = fg * c_reg + ig * gg;
        float hn = og * tanh_fast(c_reg);
        hcur[eb * H_ + d0 + ed] = hn;
        out[xi] = tanh_fast(hn + xres);

        grid_barrier();
    }
}

// ---------------------------------------------------------------------------
extern "C" void kernel_launch(void* const* d_in, const int* in_sizes, int n_in,
                              void* d_out, int out_size) {
    const float* x    = (const float*)d_in[0];
    const float* W    = (const float*)d_in[1];
    const float* U    = (const float*)d_in[2];
    const float* bias = (const float*)d_in[3];
    float* out        = (float*)d_out;

    cudaFuncSetAttribute(lstm_persistent,
                         cudaFuncAttributeMaxDynamicSharedMemorySize, SMEM_BYTES);

    init_state<<<(B_ * H_ + 255) / 256, 256>>>();

    dim3 grid_gemm(G4 / 64, (B_ * T_) / 64);   // (64, 256)
    xw_gemm<<<grid_gemm, 256>>>(x, W, bias);

    lstm_persistent<<<NCTA, NTHREADS, SMEM_BYTES>>>(U, x, out);
}

// round 4
// speedup vs baseline: 1.6854x; 1.6854x over previous
#include <cuda_runtime.h>
#include <cuda_bf16.h>
#include <math.h>

#define B_   32
#define T_   512
#define H_   1024
#define G4   4096   // 4*H

#define NCTA      128
#define NTHREADS  256

// ---------------------------------------------------------------------------
// Persistent device scratch (no cudaMalloc allowed)
// ---------------------------------------------------------------------------
__device__ float g_xz[(size_t)B_ * T_ * G4];        // [B*T, 4H] input projection
__device__ __nv_bfloat16 g_hbf[2][B_ * H_];         // double-buffered hidden (bf16)
__device__ unsigned g_bar_cnt;
__device__ volatile unsigned g_bar_gen;

// ---------------------------------------------------------------------------
// helpers
// ---------------------------------------------------------------------------
__device__ __forceinline__ unsigned f2tf32(float f) {
    unsigned u;
    asm("cvt.rna.tf32.f32 %0, %1;" : "=r"(u) : "f"(f));
    return u;
}

__device__ __forceinline__ void mma_tf32(float c[4],
                                         unsigned a0, unsigned a1, unsigned a2, unsigned a3,
                                         unsigned b0, unsigned b1) {
    asm volatile(
        "mma.sync.aligned.m16n8k8.row.col.f32.tf32.tf32.f32 "
        "{%0,%1,%2,%3}, {%4,%5,%6,%7}, {%8,%9}, {%0,%1,%2,%3};"
        : "+f"(c[0]), "+f"(c[1]), "+f"(c[2]), "+f"(c[3])
        : "r"(a0), "r"(a1), "r"(a2), "r"(a3), "r"(b0), "r"(b1));
}

__device__ __forceinline__ void mma_bf16(float c[4],
                                         unsigned a0, unsigned a1, unsigned a2, unsigned a3,
                                         unsigned b0, unsigned b1) {
    asm volatile(
        "mma.sync.aligned.m16n8k16.row.col.f32.bf16.bf16.f32 "
        "{%0,%1,%2,%3}, {%4,%5,%6,%7}, {%8,%9}, {%0,%1,%2,%3};"
        : "+f"(c[0]), "+f"(c[1]), "+f"(c[2]), "+f"(c[3])
        : "r"(a0), "r"(a1), "r"(a2), "r"(a3), "r"(b0), "r"(b1));
}

__device__ __forceinline__ unsigned pack_bf16(float lo, float hi) {
    __nv_bfloat162 v = __floats2bfloat162_rn(lo, hi);
    return *(unsigned*)&v;
}

__device__ __forceinline__ float sigf(float v) {
    return __fdividef(1.0f, 1.0f + __expf(-v));
}
__device__ __forceinline__ float tanh_fast(float v) {
    return __fdividef(2.0f, 1.0f + __expf(-2.0f * v)) - 1.0f;
}

__device__ __forceinline__ void cp16(unsigned dst_smem, const void* src) {
    asm volatile("cp.async.cg.shared.global [%0], [%1], 16;"
                 :: "r"(dst_smem), "l"(src));
}

// ---------------------------------------------------------------------------
// Kernel 0: zero h[0], reset barrier
// ---------------------------------------------------------------------------
__global__ void init_state() {
    int i = blockIdx.x * blockDim.x + threadIdx.x;
    if (i < B_ * H_) g_hbf[0][i] = __float2bfloat16(0.0f);
    if (i == 0) { g_bar_cnt = 0; g_bar_gen = 0; }
}

// ---------------------------------------------------------------------------
// Kernel 1: xz = x @ W + b  via tf32 mma (unchanged from R2).
// ---------------------------------------------------------------------------
#define AS_STRIDE 20
#define BS_STRIDE 72

__global__ __launch_bounds__(256) void xw_gemm(const float* __restrict__ X,
                                               const float* __restrict__ W,
                                               const float* __restrict__ bias) {
    __shared__ unsigned As[64 * AS_STRIDE];
    __shared__ unsigned Bs[16 * BS_STRIDE];

    const int tid   = threadIdx.x;
    const int lane  = tid & 31;
    const int w     = tid >> 5;
    const int g     = lane >> 2;
    const int tig   = lane & 3;
    const int warpM = w >> 2;
    const int warpN = w & 3;

    const int row0 = blockIdx.y * 64;
    const int col0 = blockIdx.x * 64;

    const int aRow = tid >> 2;
    const int aK   = (tid & 3) * 4;
    const int bK   = tid >> 4;
    const int bN   = (tid & 15) * 4;

    float acc[2][2][4];
#pragma unroll
    for (int i = 0; i < 2; i++)
#pragma unroll
        for (int j = 0; j < 2; j++)
#pragma unroll
            for (int k = 0; k < 4; k++) acc[i][j][k] = 0.0f;

    for (int k0 = 0; k0 < H_; k0 += 16) {
        float4 av = *(const float4*)(X + (size_t)(row0 + aRow) * H_ + k0 + aK);
        As[aRow * AS_STRIDE + aK + 0] = f2tf32(av.x);
        As[aRow * AS_STRIDE + aK + 1] = f2tf32(av.y);
        As[aRow * AS_STRIDE + aK + 2] = f2tf32(av.z);
        As[aRow * AS_STRIDE + aK + 3] = f2tf32(av.w);
        float4 bv = *(const float4*)(W + (size_t)(k0 + bK) * G4 + col0 + bN);
        Bs[bK * BS_STRIDE + bN + 0] = f2tf32(bv.x);
        Bs[bK * BS_STRIDE + bN + 1] = f2tf32(bv.y);
        Bs[bK * BS_STRIDE + bN + 2] = f2tf32(bv.z);
        Bs[bK * BS_STRIDE + bN + 3] = f2tf32(bv.w);
        __syncthreads();

#pragma unroll
        for (int kk = 0; kk < 16; kk += 8) {
            unsigned a[2][4];
#pragma unroll
            for (int mi = 0; mi < 2; mi++) {
                const unsigned* r0 = As + (warpM * 32 + mi * 16 + g) * AS_STRIDE;
                const unsigned* r1 = As + (warpM * 32 + mi * 16 + g + 8) * AS_STRIDE;
                a[mi][0] = r0[kk + tig];
                a[mi][1] = r1[kk + tig];
                a[mi][2] = r0[kk + tig + 4];
                a[mi][3] = r1[kk + tig + 4];
            }
#pragma unroll
            for (int ni = 0; ni < 2; ni++) {
                unsigned b0 = Bs[(kk + tig)     * BS_STRIDE + warpN * 16 + ni * 8 + g];
                unsigned b1 = Bs[(kk + tig + 4) * BS_STRIDE + warpN * 16 + ni * 8 + g];
#pragma unroll
                for (int mi = 0; mi < 2; mi++)
                    mma_tf32(acc[mi][ni], a[mi][0], a[mi][1], a[mi][2], a[mi][3], b0, b1);
            }
        }
        __syncthreads();
    }

#pragma unroll
    for (int mi = 0; mi < 2; mi++) {
#pragma unroll
        for (int ni = 0; ni < 2; ni++) {
            int row = row0 + warpM * 32 + mi * 16 + g;
            int col = col0 + warpN * 16 + ni * 8 + 2 * tig;
            float2 bvv = *(const float2*)(bias + col);
            float2 v0 = make_float2(acc[mi][ni][0] + bvv.x, acc[mi][ni][1] + bvv.y);
            float2 v1 = make_float2(acc[mi][ni][2] + bvv.x, acc[mi][ni][3] + bvv.y);
            *(float2*)(g_xz + (size_t)row * G4 + col)       = v0;
            *(float2*)(g_xz + (size_t)(row + 8) * G4 + col) = v1;
        }
    }
}

// ---------------------------------------------------------------------------
// Kernel 2: persistent LSTM recurrence, bf16 MMA, U in registers.
// 128 CTAs x 256 threads; CTA owns 8 hidden dims d0=cb*8 (32 z-cols).
// Warp w = k-slice (128 k each). Each warp keeps its U fragments in regs
// (64 x b32) for the whole kernel. Per step: cp.async-stage h (bf16, 64KB,
// ONE phase), 1 sync, 64 bf16 m16n8k16 MMAs (2 m-tiles x 4 n-groups), write
// k-partials, sync, gates + state + residual, prefetch next xz, grid barrier.
// ---------------------------------------------------------------------------
#define HS_STRIDE  1032                    // bf16 units per row (1024 + 8 pad)
#define RED_STRIDE 34                      // floats (32 + 2 pad)
#define HS_BYTES   (32 * HS_STRIDE * 2)    // 66048
#define RED_BYTES  (8 * 32 * RED_STRIDE * 4)
#define SMEM_BYTES (HS_BYTES + RED_BYTES)

__device__ __forceinline__ void grid_barrier() {
    __syncthreads();
    if (threadIdx.x == 0) {
        unsigned gen = g_bar_gen;
        __threadfence();
        unsigned t = atomicAdd(&g_bar_cnt, 1);
        if (t == NCTA - 1) {
            g_bar_cnt = 0;
            __threadfence();
            g_bar_gen = gen + 1;
        } else {
            while (g_bar_gen == gen) { __nanosleep(40); }
            __threadfence();
        }
    }
    __syncthreads();
}

__global__ __launch_bounds__(NTHREADS, 1) void lstm_persistent(
        const float* __restrict__ U,
        const float* __restrict__ x,
        float* __restrict__ out) {
    extern __shared__ char smem[];
    __nv_bfloat16* hS = (__nv_bfloat16*)smem;
    float*        redS = (float*)(smem + HS_BYTES);
    const unsigned hS_base = (unsigned)__cvta_generic_to_shared(hS);

    const int tid  = threadIdx.x;
    const int lane = tid & 31;
    const int ks   = tid >> 5;    // warp id = k-slice (0..7), 128 k each
    const int g    = lane >> 2;
    const int tig  = lane & 3;

    const int d0 = blockIdx.x * 8;

    // ---- preload this warp's U fragments into registers (one-time) ----
    // B frag for (kk, ng): b0 = U[k0..k0+1][col], b1 = U[k0+8..k0+9][col]
    // col = ng*H_ + d0 + g  (n-index within z tile = ng*8 + g)
    unsigned breg[8][4][2];
#pragma unroll
    for (int kk = 0; kk < 8; kk++) {
#pragma unroll
        for (int ng = 0; ng < 4; ng++) {
            const int col = ng * H_ + d0 + g;
            const int k0  = ks * 128 + kk * 16 + 2 * tig;
            breg[kk][ng][0] = pack_bf16(U[(size_t)(k0    ) * G4 + col],
                                        U[(size_t)(k0 + 1) * G4 + col]);
            breg[kk][ng][1] = pack_bf16(U[(size_t)(k0 + 8) * G4 + col],
                                        U[(size_t)(k0 + 9) * G4 + col]);
        }
    }

    const int eb = tid >> 3;     // gate-phase batch
    const int ed = tid & 7;      // gate-phase local dim
    float c_reg = 0.0f;

    // prefetch xz + residual x for t = 0
    float zin[4];
#pragma unroll
    for (int gate = 0; gate < 4; gate++)
        zin[gate] = __ldcg(&g_xz[((size_t)eb * T_ + 0) * G4 + gate * H_ + d0 + ed]);
    size_t xi = ((size_t)eb * T_ + 0) * H_ + d0 + ed;
    float xres = __ldcg(&x[xi]);

    for (int t = 0; t < T_; t++) {
        const __nv_bfloat16* hprev = g_hbf[t & 1];
        __nv_bfloat16*       hcur  = g_hbf[(t + 1) & 1];

        // ---- stage h (bf16, 64KB) via cp.async, one phase ----
#pragma unroll
        for (int i = 0; i < 16; i++) {
            int q = i * 256 + tid;        // chunk id (16B = 8 bf16)
            int r = q >> 7;               // batch row
            int c = q & 127;              // 16B chunk within row
            cp16(hS_base + (unsigned)(r * HS_STRIDE + c * 8) * 2, hprev + q * 8);
        }
        asm volatile("cp.async.commit_group;");
        asm volatile("cp.async.wait_group 0;" ::: "memory");
        __syncthreads();

        // ---- z partials: per warp [32 x 32] over its 128-k slice ----
        float acc[2][4][4];
#pragma unroll
        for (int mi = 0; mi < 2; mi++)
#pragma unroll
            for (int ng = 0; ng < 4; ng++)
#pragma unroll
                for (int q = 0; q < 4; q++) acc[mi][ng][q] = 0.0f;

#pragma unroll
        for (int kk = 0; kk < 8; kk++) {
            const int kcol = ks * 128 + kk * 16 + 2 * tig;
#pragma unroll
            for (int mi = 0; mi < 2; mi++) {
                const __nv_bfloat16* r0 = hS + (mi * 16 + g) * HS_STRIDE;
                const __nv_bfloat16* r1 = hS + (mi * 16 + g + 8) * HS_STRIDE;
                unsigned a0 = *(const unsigned*)(r0 + kcol);
                unsigned a1 = *(const unsigned*)(r1 + kcol);
                unsigned a2 = *(const unsigned*)(r0 + kcol + 8);
                unsigned a3 = *(const unsigned*)(r1 + kcol + 8);
#pragma unroll
                for (int ng = 0; ng < 4; ng++)
                    mma_bf16(acc[mi][ng], a0, a1, a2, a3,
                             breg[kk][ng][0], breg[kk][ng][1]);
            }
        }

        // ---- write k-partials ----
#pragma unroll
        for (int mi = 0; mi < 2; mi++) {
#pragma unroll
            for (int ng = 0; ng < 4; ng++) {
                const int col = ng * 8 + 2 * tig;
                float* r0 = redS + (ks * 32 + mi * 16 + g)     * RED_STRIDE + col;
                float* r1 = redS + (ks * 32 + mi * 16 + g + 8) * RED_STRIDE + col;
                *(float2*)r0 = make_float2(acc[mi][ng][0], acc[mi][ng][1]);
                *(float2*)r1 = make_float2(acc[mi][ng][2], acc[mi][ng][3]);
            }
        }
        __syncthreads();

        // ---- gates + state update + residual tanh ----
        const float* rb = redS + eb * RED_STRIDE + ed;
        float z[4];
#pragma unroll
        for (int gate = 0; gate < 4; gate++) {
            const float* p = rb + gate * 8;
            float s = zin[gate];
#pragma unroll
            for (int q = 0; q < 8; q++) s += p[q * 32 * RED_STRIDE];
            z[gate] = s;
        }
        float ig = sigf(z[0]);
        float fg = sigf(z[1]);
        float gg = tanh_fast(z[2]);
        float og = sigf(z[3]);

        c_reg = fg * c_reg + ig * gg;
        float hn = og * tanh_fast(c_reg);
        hcur[eb * H_ + d0 + ed] = __float2bfloat16(hn);
        out[xi] = tanh_fast(hn + xres);

        // ---- prefetch next step's xz + x (independent of barrier) ----
        if (t + 1 < T_) {
#pragma unroll
            for (int gate = 0; gate < 4; gate++)
                zin[gate] = __ldcg(&g_xz[((size_t)eb * T_ + t + 1) * G4 + gate * H_ + d0 + ed]);
            xi = ((size_t)eb * T_ + t + 1) * H_ + d0 + ed;
            xres = __ldcg(&x[xi]);
        }

        grid_barrier();
    }
}

// ---------------------------------------------------------------------------
extern "C" void kernel_launch(void* const* d_in, const int* in_sizes, int n_in,
                              void* d_out, int out_size) {
    const float* x    = (const float*)d_in[0];
    const float* W    = (const float*)d_in[1];
    const float* U    = (const float*)d_in[2];
    const float* bias = (const float*)d_in[3];
    float* out        = (float*)d_out;

    cudaFuncSetAttribute(lstm_persistent,
                         cudaFuncAttributeMaxDynamicSharedMemorySize, SMEM_BYTES);

    init_state<<<(B_ * H_ + 255) / 256, 256>>>();

    dim3 grid_gemm(G4 / 64, (B_ * T_) / 64);   // (64, 256)
    xw_gemm<<<grid_gemm, 256>>>(x, W, bias);

    lstm_persistent<<<NCTA, NTHREADS, SMEM_BYTES>>>(U, x, out);
}

// round 5
// speedup vs baseline: 1.8393x; 1.0913x over previous
#include <cuda_runtime.h>
#include <cuda_bf16.h>
#include <math.h>

#define B_   32
#define T_   512
#define H_   1024
#define G4   4096   // 4*H

#define NCTA      128
#define NTHREADS  256

// ---------------------------------------------------------------------------
// Persistent device scratch (no cudaMalloc allowed)
// ---------------------------------------------------------------------------
__device__ float g_xz[(size_t)B_ * T_ * G4];        // [B*T, 4H] input projection
__device__ __nv_bfloat16 g_hbf[2][B_ * H_];         // double-buffered hidden (bf16)
__device__ unsigned g_flags[NCTA];                  // per-CTA step stamps
__device__ unsigned g_gen;                          // released step stamp

// ---------------------------------------------------------------------------
// helpers
// ---------------------------------------------------------------------------
__device__ __forceinline__ void mma_bf16(float c[4],
                                         unsigned a0, unsigned a1, unsigned a2, unsigned a3,
                                         unsigned b0, unsigned b1) {
    asm volatile(
        "mma.sync.aligned.m16n8k16.row.col.f32.bf16.bf16.f32 "
        "{%0,%1,%2,%3}, {%4,%5,%6,%7}, {%8,%9}, {%0,%1,%2,%3};"
        : "+f"(c[0]), "+f"(c[1]), "+f"(c[2]), "+f"(c[3])
        : "r"(a0), "r"(a1), "r"(a2), "r"(a3), "r"(b0), "r"(b1));
}

__device__ __forceinline__ unsigned pack_bf16(float lo, float hi) {
    __nv_bfloat162 v = __floats2bfloat162_rn(lo, hi);
    return *(unsigned*)&v;
}

__device__ __forceinline__ float sigf(float v) {
    return __fdividef(1.0f, 1.0f + __expf(-v));
}
__device__ __forceinline__ float tanh_fast(float v) {
    return __fdividef(2.0f, 1.0f + __expf(-2.0f * v)) - 1.0f;
}

__device__ __forceinline__ void cp16(unsigned dst_smem, const void* src) {
    asm volatile("cp.async.cg.shared.global [%0], [%1], 16;"
                 :: "r"(dst_smem), "l"(src));
}

__device__ __forceinline__ unsigned ld_acq(const unsigned* p) {
    unsigned v;
    asm volatile("ld.acquire.gpu.global.b32 %0, [%1];" : "=r"(v) : "l"(p));
    return v;
}
__device__ __forceinline__ void st_rel(unsigned* p, unsigned v) {
    asm volatile("st.release.gpu.global.b32 [%0], %1;" :: "l"(p), "r"(v));
}

// ---------------------------------------------------------------------------
// Kernel 0: zero h[0], reset barrier state
// ---------------------------------------------------------------------------
__global__ void init_state() {
    int i = blockIdx.x * blockDim.x + threadIdx.x;
    if (i < B_ * H_) g_hbf[0][i] = __float2bfloat16(0.0f);
    if (i < NCTA) g_flags[i] = 0;
    if (i == 0) g_gen = 0;
}

// ---------------------------------------------------------------------------
// Kernel 1: xz = x @ W + b  via bf16 m16n8k16.  M=16384, N=4096, K=1024
// CTA tile 64x64, BK=16, 8 warps 2x4, warp tile 32x16.
// As32: [64 rows][12 words]  (word = bf16 k-pair; stride 12 -> conflict-free frags)
// Bs32: [8 kp][68 words]     (word = bf16 k-pair at column n)
// ---------------------------------------------------------------------------
#define AS32_STRIDE 12
#define BS32_STRIDE 68

__global__ __launch_bounds__(256) void xw_gemm(const float* __restrict__ X,
                                               const float* __restrict__ W,
                                               const float* __restrict__ bias) {
    __shared__ unsigned As32[64 * AS32_STRIDE];
    __shared__ unsigned Bs32[8 * BS32_STRIDE];

    const int tid   = threadIdx.x;
    const int lane  = tid & 31;
    const int w     = tid >> 5;
    const int g     = lane >> 2;
    const int tig   = lane & 3;
    const int warpM = w >> 2;      // 0..1
    const int warpN = w & 3;       // 0..3

    const int row0 = blockIdx.y * 64;
    const int col0 = blockIdx.x * 64;

    // staging maps
    const int aRow = tid >> 2;           // 0..63
    const int aC   = tid & 3;            // k-quad (4 floats at k0+4*aC)
    const int bKp  = tid >> 4;           // 0..7  (k pair index), tid<128 only
    const int bNq  = tid & 15;           // 0..15 (n quad)

    float acc[2][2][4];
#pragma unroll
    for (int i = 0; i < 2; i++)
#pragma unroll
        for (int j = 0; j < 2; j++)
#pragma unroll
            for (int k = 0; k < 4; k++) acc[i][j][k] = 0.0f;

    for (int k0 = 0; k0 < H_; k0 += 16) {
        // stage A: 64 rows x 16 k (fp32 -> bf16 pairs)
        {
            float4 av = *(const float4*)(X + (size_t)(row0 + aRow) * H_ + k0 + 4 * aC);
            uint2 p;
            p.x = pack_bf16(av.x, av.y);
            p.y = pack_bf16(av.z, av.w);
            *(uint2*)(As32 + aRow * AS32_STRIDE + 2 * aC) = p;
        }
        // stage B: 16 k x 64 n (two k-rows packed per word)
        if (tid < 128) {
            const float* wr0 = W + (size_t)(k0 + 2 * bKp)     * G4 + col0 + 4 * bNq;
            const float* wr1 = W + (size_t)(k0 + 2 * bKp + 1) * G4 + col0 + 4 * bNq;
            float4 w0 = *(const float4*)wr0;
            float4 w1 = *(const float4*)wr1;
            uint4 p;
            p.x = pack_bf16(w0.x, w1.x);
            p.y = pack_bf16(w0.y, w1.y);
            p.z = pack_bf16(w0.z, w1.z);
            p.w = pack_bf16(w0.w, w1.w);
            *(uint4*)(Bs32 + bKp * BS32_STRIDE + 4 * bNq) = p;
        }
        __syncthreads();

        // compute: 2 mi x 2 ni m16n8k16 per warp
        unsigned a[2][4];
#pragma unroll
        for (int mi = 0; mi < 2; mi++) {
            const int r = warpM * 32 + mi * 16 + g;
            a[mi][0] = As32[r * AS32_STRIDE + tig];
            a[mi][1] = As32[(r + 8) * AS32_STRIDE + tig];
            a[mi][2] = As32[r * AS32_STRIDE + tig + 4];
            a[mi][3] = As32[(r + 8) * AS32_STRIDE + tig + 4];
        }
#pragma unroll
        for (int ni = 0; ni < 2; ni++) {
            const int n = warpN * 16 + ni * 8 + g;
            unsigned b0 = Bs32[tig * BS32_STRIDE + n];
            unsigned b1 = Bs32[(tig + 4) * BS32_STRIDE + n];
#pragma unroll
            for (int mi = 0; mi < 2; mi++)
                mma_bf16(acc[mi][ni], a[mi][0], a[mi][1], a[mi][2], a[mi][3], b0, b1);
        }
        __syncthreads();
    }

    // epilogue: + bias, store fp32
#pragma unroll
    for (int mi = 0; mi < 2; mi++) {
#pragma unroll
        for (int ni = 0; ni < 2; ni++) {
            int row = row0 + warpM * 32 + mi * 16 + g;
            int col = col0 + warpN * 16 + ni * 8 + 2 * tig;
            float2 bvv = *(const float2*)(bias + col);
            float2 v0 = make_float2(acc[mi][ni][0] + bvv.x, acc[mi][ni][1] + bvv.y);
            float2 v1 = make_float2(acc[mi][ni][2] + bvv.x, acc[mi][ni][3] + bvv.y);
            *(float2*)(g_xz + (size_t)row * G4 + col)       = v0;
            *(float2*)(g_xz + (size_t)(row + 8) * G4 + col) = v1;
        }
    }
}

// ---------------------------------------------------------------------------
// Kernel 2: persistent LSTM recurrence, bf16 MMA, U in registers,
// atomic-free flag barrier.
// ---------------------------------------------------------------------------
#define HS_STRIDE  1032                    // bf16 units per row (1024 + 8 pad)
#define RED_STRIDE 34                      // floats (32 + 2 pad)
#define HS_BYTES   (32 * HS_STRIDE * 2)
#define RED_BYTES  (8 * 32 * RED_STRIDE * 4)
#define SMEM_BYTES (HS_BYTES + RED_BYTES)

__global__ __launch_bounds__(NTHREADS, 1) void lstm_persistent(
        const float* __restrict__ U,
        const float* __restrict__ x,
        float* __restrict__ out) {
    extern __shared__ char smem[];
    __nv_bfloat16* hS = (__nv_bfloat16*)smem;
    float*        redS = (float*)(smem + HS_BYTES);
    const unsigned hS_base = (unsigned)__cvta_generic_to_shared(hS);

    const int tid  = threadIdx.x;
    const int lane = tid & 31;
    const int ks   = tid >> 5;    // warp id = k-slice (0..7), 128 k each
    const int g    = lane >> 2;
    const int tig  = lane & 3;

    const int d0 = blockIdx.x * 8;

    // ---- preload this warp's U fragments into registers (one-time) ----
    unsigned breg[8][4][2];
#pragma unroll
    for (int kk = 0; kk < 8; kk++) {
#pragma unroll
        for (int ng = 0; ng < 4; ng++) {
            const int col = ng * H_ + d0 + g;
            const int k0  = ks * 128 + kk * 16 + 2 * tig;
            breg[kk][ng][0] = pack_bf16(U[(size_t)(k0    ) * G4 + col],
                                        U[(size_t)(k0 + 1) * G4 + col]);
            breg[kk][ng][1] = pack_bf16(U[(size_t)(k0 + 8) * G4 + col],
                                        U[(size_t)(k0 + 9) * G4 + col]);
        }
    }

    const int eb = tid >> 3;     // gate-phase batch
    const int ed = tid & 7;      // gate-phase local dim
    float c_reg = 0.0f;

    // prefetch xz + residual x for t = 0 (stream order covers xw_gemm writes)
    float zin[4];
#pragma unroll
    for (int gate = 0; gate < 4; gate++)
        zin[gate] = __ldcg(&g_xz[((size_t)eb * T_ + 0) * G4 + gate * H_ + d0 + ed]);
    size_t xi = ((size_t)eb * T_ + 0) * H_ + d0 + ed;
    float xres = __ldcg(&x[xi]);

    for (int t = 0; t < T_; t++) {
        const unsigned stamp = (unsigned)(t + 1);
        const __nv_bfloat16* hprev = g_hbf[t & 1];
        __nv_bfloat16*       hcur  = g_hbf[(t + 1) & 1];

        // ---- stage h (bf16, 64KB) via cp.async, one phase ----
#pragma unroll
        for (int i = 0; i < 16; i++) {
            int q = i * 256 + tid;        // 16B chunk id
            int r = q >> 7;
            int c = q & 127;
            cp16(hS_base + (unsigned)(r * HS_STRIDE + c * 8) * 2, hprev + q * 8);
        }
        asm volatile("cp.async.commit_group;");
        asm volatile("cp.async.wait_group 0;" ::: "memory");
        __syncthreads();

        // ---- z partials: per warp [32 x 32] over its 128-k slice ----
        float acc[2][4][4];
#pragma unroll
        for (int mi = 0; mi < 2; mi++)
#pragma unroll
            for (int ng = 0; ng < 4; ng++)
#pragma unroll
                for (int q = 0; q < 4; q++) acc[mi][ng][q] = 0.0f;

#pragma unroll
        for (int kk = 0; kk < 8; kk++) {
            const int kcol = ks * 128 + kk * 16 + 2 * tig;
#pragma unroll
            for (int mi = 0; mi < 2; mi++) {
                const __nv_bfloat16* r0 = hS + (mi * 16 + g) * HS_STRIDE;
                const __nv_bfloat16* r1 = hS + (mi * 16 + g + 8) * HS_STRIDE;
                unsigned a0 = *(const unsigned*)(r0 + kcol);
                unsigned a1 = *(const unsigned*)(r1 + kcol);
                unsigned a2 = *(const unsigned*)(r0 + kcol + 8);
                unsigned a3 = *(const unsigned*)(r1 + kcol + 8);
#pragma unroll
                for (int ng = 0; ng < 4; ng++)
                    mma_bf16(acc[mi][ng], a0, a1, a2, a3,
                             breg[kk][ng][0], breg[kk][ng][1]);
            }
        }

        // ---- write k-partials ----
#pragma unroll
        for (int mi = 0; mi < 2; mi++) {
#pragma unroll
            for (int ng = 0; ng < 4; ng++) {
                const int col = ng * 8 + 2 * tig;
                float* r0 = redS + (ks * 32 + mi * 16 + g)     * RED_STRIDE + col;
                float* r1 = redS + (ks * 32 + mi * 16 + g + 8) * RED_STRIDE + col;
                *(float2*)r0 = make_float2(acc[mi][ng][0], acc[mi][ng][1]);
                *(float2*)r1 = make_float2(acc[mi][ng][2], acc[mi][ng][3]);
            }
        }
        __syncthreads();

        // ---- gates + state update ----
        const float* rb = redS + eb * RED_STRIDE + ed;
        float z[4];
#pragma unroll
        for (int gate = 0; gate < 4; gate++) {
            const float* p = rb + gate * 8;
            float s = zin[gate];
#pragma unroll
            for (int q = 0; q < 8; q++) s += p[q * 32 * RED_STRIDE];
            z[gate] = s;
        }
        float ig = sigf(z[0]);
        float fg = sigf(z[1]);
        float gg = tanh_fast(z[2]);
        float og = sigf(z[3]);

        c_reg = fg * c_reg + ig * gg;
        float hn = og * tanh_fast(c_reg);
        hcur[eb * H_ + d0 + ed] = __float2bfloat16(hn);

        // ---- publish h ASAP ----
        __syncthreads();                       // CTA's h chunk complete
        if (tid == 0) st_rel(&g_flags[blockIdx.x], stamp);

        // ---- off-critical-path work while peers arrive ----
        out[xi] = tanh_fast(hn + xres);
        if (t + 1 < T_) {
#pragma unroll
            for (int gate = 0; gate < 4; gate++)
                zin[gate] = __ldcg(&g_xz[((size_t)eb * T_ + t + 1) * G4 + gate * H_ + d0 + ed]);
            xi = ((size_t)eb * T_ + t + 1) * H_ + d0 + ed;
            xres = __ldcg(&x[xi]);
        }

        // ---- CTA0 aggregates; everyone waits on gen ----
        if (blockIdx.x == 0) {
            if (tid < NCTA) {
                while (ld_acq(&g_flags[tid]) < stamp) { }
            }
            __syncthreads();
            if (tid == 0) st_rel(&g_gen, stamp);
        }
        if (tid == 0) {
            while (ld_acq(&g_gen) < stamp) { }
        }
        __syncthreads();
    }
}

// ---------------------------------------------------------------------------
extern "C" void kernel_launch(void* const* d_in, const int* in_sizes, int n_in,
                              void* d_out, int out_size) {
    const float* x    = (const float*)d_in[0];
    const float* W    = (const float*)d_in[1];
    const float* U    = (const float*)d_in[2];
    const float* bias = (const float*)d_in[3];
    float* out        = (float*)d_out;

    cudaFuncSetAttribute(lstm_persistent,
                         cudaFuncAttributeMaxDynamicSharedMemorySize, SMEM_BYTES);

    init_state<<<(B_ * H_ + 255) / 256, 256>>>();

    dim3 grid_gemm(G4 / 64, (B_ * T_) / 64);   // (64, 256)
    xw_gemm<<<grid_gemm, 256>>>(x, W, bias);

    lstm_persistent<<<NCTA, NTHREADS, SMEM_BYTES>>>(U, x, out);
}

// round 6
// speedup vs baseline: 1.9104x; 1.0387x over previous
#include <cuda_runtime.h>
#include <cuda_bf16.h>
#include <math.h>

#define B_   32
#define T_   512
#define H_   1024
#define G4   4096   // 4*H

#define NCTA      128
#define NTHREADS  256

// ---------------------------------------------------------------------------
// Persistent device scratch (no cudaMalloc allowed)
// ---------------------------------------------------------------------------
__device__ float g_xz[(size_t)B_ * T_ * G4];        // [B*T, 4H] input projection
__device__ __nv_bfloat16 g_hbf[2][B_ * H_];         // double-buffered hidden (bf16)
__device__ unsigned g_flags[NCTA * 8];              // per-CTA step stamps (32B stride)

// ---------------------------------------------------------------------------
// helpers
// ---------------------------------------------------------------------------
__device__ __forceinline__ void mma_bf16(float c[4],
                                         unsigned a0, unsigned a1, unsigned a2, unsigned a3,
                                         unsigned b0, unsigned b1) {
    asm volatile(
        "mma.sync.aligned.m16n8k16.row.col.f32.bf16.bf16.f32 "
        "{%0,%1,%2,%3}, {%4,%5,%6,%7}, {%8,%9}, {%0,%1,%2,%3};"
        : "+f"(c[0]), "+f"(c[1]), "+f"(c[2]), "+f"(c[3])
        : "r"(a0), "r"(a1), "r"(a2), "r"(a3), "r"(b0), "r"(b1));
}

__device__ __forceinline__ unsigned pack_bf16(float lo, float hi) {
    __nv_bfloat162 v = __floats2bfloat162_rn(lo, hi);
    return *(unsigned*)&v;
}

__device__ __forceinline__ float sigf(float v) {
    return __fdividef(1.0f, 1.0f + __expf(-v));
}
__device__ __forceinline__ float tanh_fast(float v) {
    return __fdividef(2.0f, 1.0f + __expf(-2.0f * v)) - 1.0f;
}

__device__ __forceinline__ void cp16(unsigned dst_smem, const void* src) {
    asm volatile("cp.async.cg.shared.global [%0], [%1], 16;"
                 :: "r"(dst_smem), "l"(src));
}

__device__ __forceinline__ unsigned ld_acq(const unsigned* p) {
    unsigned v;
    asm volatile("ld.acquire.gpu.global.b32 %0, [%1];" : "=r"(v) : "l"(p));
    return v;
}
__device__ __forceinline__ void st_rel(unsigned* p, unsigned v) {
    asm volatile("st.release.gpu.global.b32 [%0], %1;" :: "l"(p), "r"(v));
}

// ---------------------------------------------------------------------------
// Kernel 1: xz = x @ W + b  via bf16 m16n8k16 (CTA(0,0) also re-inits state).
// ---------------------------------------------------------------------------
#define AS32_STRIDE 12
#define BS32_STRIDE 68

__global__ __launch_bounds__(256) void xw_gemm(const float* __restrict__ X,
                                               const float* __restrict__ W,
                                               const float* __restrict__ bias) {
    __shared__ unsigned As32[64 * AS32_STRIDE];
    __shared__ unsigned Bs32[8 * BS32_STRIDE];

    const int tid   = threadIdx.x;
    const int lane  = tid & 31;
    const int w     = tid >> 5;
    const int g     = lane >> 2;
    const int tig   = lane & 3;
    const int warpM = w >> 2;
    const int warpN = w & 3;

    // ---- embedded per-replay state re-init (tiny, runs alongside GEMM) ----
    if (blockIdx.x == 0 && blockIdx.y == 0) {
        for (int i = tid; i < B_ * H_; i += 256)
            g_hbf[0][i] = __float2bfloat16(0.0f);
        for (int i = tid; i < NCTA * 8; i += 256)
            g_flags[i] = 0;
    }

    const int row0 = blockIdx.y * 64;
    const int col0 = blockIdx.x * 64;

    const int aRow = tid >> 2;
    const int aC   = tid & 3;
    const int bKp  = tid >> 4;
    const int bNq  = tid & 15;

    float acc[2][2][4];
#pragma unroll
    for (int i = 0; i < 2; i++)
#pragma unroll
        for (int j = 0; j < 2; j++)
#pragma unroll
            for (int k = 0; k < 4; k++) acc[i][j][k] = 0.0f;

    for (int k0 = 0; k0 < H_; k0 += 16) {
        {
            float4 av = *(const float4*)(X + (size_t)(row0 + aRow) * H_ + k0 + 4 * aC);
            uint2 p;
            p.x = pack_bf16(av.x, av.y);
            p.y = pack_bf16(av.z, av.w);
            *(uint2*)(As32 + aRow * AS32_STRIDE + 2 * aC) = p;
        }
        if (tid < 128) {
            const float* wr0 = W + (size_t)(k0 + 2 * bKp)     * G4 + col0 + 4 * bNq;
            const float* wr1 = W + (size_t)(k0 + 2 * bKp + 1) * G4 + col0 + 4 * bNq;
            float4 w0 = *(const float4*)wr0;
            float4 w1 = *(const float4*)wr1;
            uint4 p;
            p.x = pack_bf16(w0.x, w1.x);
            p.y = pack_bf16(w0.y, w1.y);
            p.z = pack_bf16(w0.z, w1.z);
            p.w = pack_bf16(w0.w, w1.w);
            *(uint4*)(Bs32 + bKp * BS32_STRIDE + 4 * bNq) = p;
        }
        __syncthreads();

        unsigned a[2][4];
#pragma unroll
        for (int mi = 0; mi < 2; mi++) {
            const int r = warpM * 32 + mi * 16 + g;
            a[mi][0] = As32[r * AS32_STRIDE + tig];
            a[mi][1] = As32[(r + 8) * AS32_STRIDE + tig];
            a[mi][2] = As32[r * AS32_STRIDE + tig + 4];
            a[mi][3] = As32[(r + 8) * AS32_STRIDE + tig + 4];
        }
#pragma unroll
        for (int ni = 0; ni < 2; ni++) {
            const int n = warpN * 16 + ni * 8 + g;
            unsigned b0 = Bs32[tig * BS32_STRIDE + n];
            unsigned b1 = Bs32[(tig + 4) * BS32_STRIDE + n];
#pragma unroll
            for (int mi = 0; mi < 2; mi++)
                mma_bf16(acc[mi][ni], a[mi][0], a[mi][1], a[mi][2], a[mi][3], b0, b1);
        }
        __syncthreads();
    }

#pragma unroll
    for (int mi = 0; mi < 2; mi++) {
#pragma unroll
        for (int ni = 0; ni < 2; ni++) {
            int row = row0 + warpM * 32 + mi * 16 + g;
            int col = col0 + warpN * 16 + ni * 8 + 2 * tig;
            float2 bvv = *(const float2*)(bias + col);
            float2 v0 = make_float2(acc[mi][ni][0] + bvv.x, acc[mi][ni][1] + bvv.y);
            float2 v1 = make_float2(acc[mi][ni][2] + bvv.x, acc[mi][ni][3] + bvv.y);
            *(float2*)(g_xz + (size_t)row * G4 + col)       = v0;
            *(float2*)(g_xz + (size_t)(row + 8) * G4 + col) = v1;
        }
    }
}

// ---------------------------------------------------------------------------
// Kernel 2: persistent LSTM recurrence.
// - U fragments in registers (per warp, whole kernel)
// - per-warp k-slice h staging via cp.async (no block sync before MMA)
// - one-hop flat flag barrier (every CTA polls all 128 flags)
// ---------------------------------------------------------------------------
#define HS_STRIDE  1032                    // bf16 units per row (1024 + 8 pad)
#define RED_STRIDE 40                      // floats -> conflict-free gate loads
#define HS_BYTES   (32 * HS_STRIDE * 2)
#define RED_BYTES  (8 * 32 * RED_STRIDE * 4)
#define SMEM_BYTES (HS_BYTES + RED_BYTES)

__global__ __launch_bounds__(NTHREADS, 1) void lstm_persistent(
        const float* __restrict__ U,
        const float* __restrict__ x,
        float* __restrict__ out) {
    extern __shared__ char smem[];
    __nv_bfloat16* hS = (__nv_bfloat16*)smem;
    float*        redS = (float*)(smem + HS_BYTES);
    const unsigned hS_base = (unsigned)__cvta_generic_to_shared(hS);

    const int tid  = threadIdx.x;
    const int lane = tid & 31;
    const int ks   = tid >> 5;    // warp id = k-slice (0..7), 128 k each
    const int g    = lane >> 2;
    const int tig  = lane & 3;

    const int d0 = blockIdx.x * 8;
    const int fidx = ((tid + blockIdx.x) & (NCTA - 1)) * 8;  // rotated flag slot

    // ---- preload this warp's U fragments into registers (one-time) ----
    unsigned breg[8][4][2];
#pragma unroll
    for (int kk = 0; kk < 8; kk++) {
#pragma unroll
        for (int ng = 0; ng < 4; ng++) {
            const int col = ng * H_ + d0 + g;
            const int k0  = ks * 128 + kk * 16 + 2 * tig;
            breg[kk][ng][0] = pack_bf16(U[(size_t)(k0    ) * G4 + col],
                                        U[(size_t)(k0 + 1) * G4 + col]);
            breg[kk][ng][1] = pack_bf16(U[(size_t)(k0 + 8) * G4 + col],
                                        U[(size_t)(k0 + 9) * G4 + col]);
        }
    }

    const int eb = tid >> 3;     // gate-phase batch
    const int ed = tid & 7;      // gate-phase local dim
    float c_reg = 0.0f;

    // prefetch xz + residual x for t = 0 (stream order covers xw_gemm writes)
    float zin[4];
#pragma unroll
    for (int gate = 0; gate < 4; gate++)
        zin[gate] = __ldcg(&g_xz[((size_t)eb * T_ + 0) * G4 + gate * H_ + d0 + ed]);
    size_t xi = ((size_t)eb * T_ + 0) * H_ + d0 + ed;
    float xres = __ldcg(&x[xi]);

    for (int t = 0; t < T_; t++) {
        const unsigned stamp = (unsigned)(t + 1);
        const __nv_bfloat16* hprev = g_hbf[t & 1];
        __nv_bfloat16*       hcur  = g_hbf[(t + 1) & 1];

        // ---- per-warp k-slice staging: warp ks loads h[:, ks*128 .. +128) ----
#pragma unroll
        for (int i = 0; i < 16; i++) {
            int q = i * 32 + lane;        // 0..511 chunk of warp's 8KB slice
            int r = q >> 4;               // batch row 0..31
            int c = q & 15;               // 16B chunk within 256B row-slice
            cp16(hS_base + (unsigned)(r * HS_STRIDE + ks * 128 + c * 8) * 2,
                 hprev + r * H_ + ks * 128 + c * 8);
        }
        asm volatile("cp.async.commit_group;");
        asm volatile("cp.async.wait_group 0;" ::: "memory");
        // no __syncthreads: each warp consumes only its own slice

        // ---- z partials: per warp [32 x 32] over its 128-k slice ----
        float acc[2][4][4];
#pragma unroll
        for (int mi = 0; mi < 2; mi++)
#pragma unroll
            for (int ng = 0; ng < 4; ng++)
#pragma unroll
                for (int q = 0; q < 4; q++) acc[mi][ng][q] = 0.0f;

#pragma unroll
        for (int kk = 0; kk < 8; kk++) {
            const int kcol = ks * 128 + kk * 16 + 2 * tig;
#pragma unroll
            for (int mi = 0; mi < 2; mi++) {
                const __nv_bfloat16* r0 = hS + (mi * 16 + g) * HS_STRIDE;
                const __nv_bfloat16* r1 = hS + (mi * 16 + g + 8) * HS_STRIDE;
                unsigned a0 = *(const unsigned*)(r0 + kcol);
                unsigned a1 = *(const unsigned*)(r1 + kcol);
                unsigned a2 = *(const unsigned*)(r0 + kcol + 8);
                unsigned a3 = *(const unsigned*)(r1 + kcol + 8);
#pragma unroll
                for (int ng = 0; ng < 4; ng++)
                    mma_bf16(acc[mi][ng], a0, a1, a2, a3,
                             breg[kk][ng][0], breg[kk][ng][1]);
            }
        }

        // ---- write k-partials ----
#pragma unroll
        for (int mi = 0; mi < 2; mi++) {
#pragma unroll
            for (int ng = 0; ng < 4; ng++) {
                const int col = ng * 8 + 2 * tig;
                float* r0 = redS + (ks * 32 + mi * 16 + g)     * RED_STRIDE + col;
                float* r1 = redS + (ks * 32 + mi * 16 + g + 8) * RED_STRIDE + col;
                *(float2*)r0 = make_float2(acc[mi][ng][0], acc[mi][ng][1]);
                *(float2*)r1 = make_float2(acc[mi][ng][2], acc[mi][ng][3]);
            }
        }
        __syncthreads();

        // ---- gates + state update ----
        const float* rb = redS + eb * RED_STRIDE + ed;
        float z[4];
#pragma unroll
        for (int gate = 0; gate < 4; gate++) {
            const float* p = rb + gate * 8;
            float s = zin[gate];
#pragma unroll
            for (int q = 0; q < 8; q++) s += p[q * 32 * RED_STRIDE];
            z[gate] = s;
        }
        float ig = sigf(z[0]);
        float fg = sigf(z[1]);
        float gg = tanh_fast(z[2]);
        float og = sigf(z[3]);

        c_reg = fg * c_reg + ig * gg;
        float hn = og * tanh_fast(c_reg);
        hcur[eb * H_ + d0 + ed] = __float2bfloat16(hn);

        // ---- publish h ----
        __syncthreads();                       // CTA's h chunk complete
        if (tid == 0) st_rel(&g_flags[blockIdx.x * 8], stamp);

        // ---- off-critical-path work while peers arrive ----
        out[xi] = tanh_fast(hn + xres);
        if (t + 1 < T_) {
#pragma unroll
            for (int gate = 0; gate < 4; gate++)
                zin[gate] = __ldcg(&g_xz[((size_t)eb * T_ + t + 1) * G4 + gate * H_ + d0 + ed]);
            xi = ((size_t)eb * T_ + t + 1) * H_ + d0 + ed;
            xres = __ldcg(&x[xi]);
        }

        // ---- one-hop flat barrier: all CTAs poll all flags ----
        if (tid < NCTA) {
            while (ld_acq(&g_flags[fidx]) < stamp) { }
        }
        __syncthreads();
    }
}

// ---------------------------------------------------------------------------
extern "C" void kernel_launch(void* const* d_in, const int* in_sizes, int n_in,
                              void* d_out, int out_size) {
    const float* x    = (const float*)d_in[0];
    const float* W    = (const float*)d_in[1];
    const float* U    = (const float*)d_in[2];
    const float* bias = (const float*)d_in[3];
    float* out        = (float*)d_out;

    cudaFuncSetAttribute(lstm_persistent,
                         cudaFuncAttributeMaxDynamicSharedMemorySize, SMEM_BYTES);

    dim3 grid_gemm(G4 / 64, (B_ * T_) / 64);   // (64, 256)
    xw_gemm<<<grid_gemm, 256>>>(x, W, bias);

    lstm_persistent<<<NCTA, NTHREADS, SMEM_BYTES>>>(U, x, out);
}

// round 7
// speedup vs baseline: 1.9794x; 1.0361x over previous
#include <cuda_runtime.h>
#include <cuda_bf16.h>
#include <math.h>

#define B_   32
#define T_   512
#define H_   1024
#define G4   4096   // 4*H

#define NCTA      128
#define NTHREADS  256

// ---------------------------------------------------------------------------
// Persistent device scratch (no cudaMalloc allowed)
// ---------------------------------------------------------------------------
__device__ float g_xz[(size_t)B_ * T_ * G4];        // [B*T, 4H] input projection
__device__ __nv_bfloat16 g_hbf[2][B_ * H_];         // double-buffered hidden (bf16)
__device__ unsigned g_flags[NCTA * 8];              // per-CTA step stamps (32B stride)

// ---------------------------------------------------------------------------
// helpers
// ---------------------------------------------------------------------------
__device__ __forceinline__ void mma_bf16(float c[4],
                                         unsigned a0, unsigned a1, unsigned a2, unsigned a3,
                                         unsigned b0, unsigned b1) {
    asm volatile(
        "mma.sync.aligned.m16n8k16.row.col.f32.bf16.bf16.f32 "
        "{%0,%1,%2,%3}, {%4,%5,%6,%7}, {%8,%9}, {%0,%1,%2,%3};"
        : "+f"(c[0]), "+f"(c[1]), "+f"(c[2]), "+f"(c[3])
        : "r"(a0), "r"(a1), "r"(a2), "r"(a3), "r"(b0), "r"(b1));
}

__device__ __forceinline__ unsigned pack_bf16(float lo, float hi) {
    __nv_bfloat162 v = __floats2bfloat162_rn(lo, hi);
    return *(unsigned*)&v;
}

__device__ __forceinline__ float sigf(float v) {
    return __fdividef(1.0f, 1.0f + __expf(-v));
}
__device__ __forceinline__ float tanh_fast(float v) {
    return __fdividef(2.0f, 1.0f + __expf(-2.0f * v)) - 1.0f;
}

__device__ __forceinline__ void cp16(unsigned dst_smem, const void* src) {
    asm volatile("cp.async.cg.shared.global [%0], [%1], 16;"
                 :: "r"(dst_smem), "l"(src));
}

__device__ __forceinline__ unsigned ld_acq(const unsigned* p) {
    unsigned v;
    asm volatile("ld.acquire.gpu.global.b32 %0, [%1];" : "=r"(v) : "l"(p));
    return v;
}
__device__ __forceinline__ void st_rel(unsigned* p, unsigned v) {
    asm volatile("st.release.gpu.global.b32 [%0], %1;" :: "l"(p), "r"(v));
}

// ---------------------------------------------------------------------------
// Kernel 1: xz = x @ W + b  via bf16 m16n8k16 (CTA(0,0) also re-inits state).
// ---------------------------------------------------------------------------
#define AS32_STRIDE 12
#define BS32_STRIDE 68

__global__ __launch_bounds__(256) void xw_gemm(const float* __restrict__ X,
                                               const float* __restrict__ W,
                                               const float* __restrict__ bias) {
    __shared__ unsigned As32[64 * AS32_STRIDE];
    __shared__ unsigned Bs32[8 * BS32_STRIDE];

    const int tid   = threadIdx.x;
    const int lane  = tid & 31;
    const int w     = tid >> 5;
    const int g     = lane >> 2;
    const int tig   = lane & 3;
    const int warpM = w >> 2;
    const int warpN = w & 3;

    // ---- embedded per-replay state re-init (tiny, runs alongside GEMM) ----
    if (blockIdx.x == 0 && blockIdx.y == 0) {
        for (int i = tid; i < B_ * H_; i += 256)
            g_hbf[0][i] = __float2bfloat16(0.0f);
        for (int i = tid; i < NCTA * 8; i += 256)
            g_flags[i] = 0;
    }

    const int row0 = blockIdx.y * 64;
    const int col0 = blockIdx.x * 64;

    const int aRow = tid >> 2;
    const int aC   = tid & 3;
    const int bKp  = tid >> 4;
    const int bNq  = tid & 15;

    float acc[2][2][4];
#pragma unroll
    for (int i = 0; i < 2; i++)
#pragma unroll
        for (int j = 0; j < 2; j++)
#pragma unroll
            for (int k = 0; k < 4; k++) acc[i][j][k] = 0.0f;

    for (int k0 = 0; k0 < H_; k0 += 16) {
        {
            float4 av = *(const float4*)(X + (size_t)(row0 + aRow) * H_ + k0 + 4 * aC);
            uint2 p;
            p.x = pack_bf16(av.x, av.y);
            p.y = pack_bf16(av.z, av.w);
            *(uint2*)(As32 + aRow * AS32_STRIDE + 2 * aC) = p;
        }
        if (tid < 128) {
            const float* wr0 = W + (size_t)(k0 + 2 * bKp)     * G4 + col0 + 4 * bNq;
            const float* wr1 = W + (size_t)(k0 + 2 * bKp + 1) * G4 + col0 + 4 * bNq;
            float4 w0 = *(const float4*)wr0;
            float4 w1 = *(const float4*)wr1;
            uint4 p;
            p.x = pack_bf16(w0.x, w1.x);
            p.y = pack_bf16(w0.y, w1.y);
            p.z = pack_bf16(w0.z, w1.z);
            p.w = pack_bf16(w0.w, w1.w);
            *(uint4*)(Bs32 + bKp * BS32_STRIDE + 4 * bNq) = p;
        }
        __syncthreads();

        unsigned a[2][4];
#pragma unroll
        for (int mi = 0; mi < 2; mi++) {
            const int r = warpM * 32 + mi * 16 + g;
            a[mi][0] = As32[r * AS32_STRIDE + tig];
            a[mi][1] = As32[(r + 8) * AS32_STRIDE + tig];
            a[mi][2] = As32[r * AS32_STRIDE + tig + 4];
            a[mi][3] = As32[(r + 8) * AS32_STRIDE + tig + 4];
        }
#pragma unroll
        for (int ni = 0; ni < 2; ni++) {
            const int n = warpN * 16 + ni * 8 + g;
            unsigned b0 = Bs32[tig * BS32_STRIDE + n];
            unsigned b1 = Bs32[(tig + 4) * BS32_STRIDE + n];
#pragma unroll
            for (int mi = 0; mi < 2; mi++)
                mma_bf16(acc[mi][ni], a[mi][0], a[mi][1], a[mi][2], a[mi][3], b0, b1);
        }
        __syncthreads();
    }

#pragma unroll
    for (int mi = 0; mi < 2; mi++) {
#pragma unroll
        for (int ni = 0; ni < 2; ni++) {
            int row = row0 + warpM * 32 + mi * 16 + g;
            int col = col0 + warpN * 16 + ni * 8 + 2 * tig;
            float2 bvv = *(const float2*)(bias + col);
            float2 v0 = make_float2(acc[mi][ni][0] + bvv.x, acc[mi][ni][1] + bvv.y);
            float2 v1 = make_float2(acc[mi][ni][2] + bvv.x, acc[mi][ni][3] + bvv.y);
            *(float2*)(g_xz + (size_t)row * G4 + col)       = v0;
            *(float2*)(g_xz + (size_t)(row + 8) * G4 + col) = v1;
        }
    }
}

// ---------------------------------------------------------------------------
// Kernel 2: persistent LSTM recurrence.
// - U fragments in registers (per warp, whole kernel)
// - per-warp k-slice h staging via cp.async (no block sync before MMA)
// - one-hop flat flag barrier (every CTA polls all 128 flags)
// ---------------------------------------------------------------------------
#define HS_STRIDE  1032                    // bf16 units per row (1024 + 8 pad)
#define RED_STRIDE 40                      // floats -> conflict-free gate loads
#define HS_BYTES   (32 * HS_STRIDE * 2)
#define RED_BYTES  (8 * 32 * RED_STRIDE * 4)
#define SMEM_BYTES (HS_BYTES + RED_BYTES)

__global__ __launch_bounds__(NTHREADS, 1) void lstm_persistent(
        const float* __restrict__ U,
        const float* __restrict__ x,
        float* __restrict__ out) {
    extern __shared__ char smem[];
    __nv_bfloat16* hS = (__nv_bfloat16*)smem;
    float*        redS = (float*)(smem + HS_BYTES);
    const unsigned hS_base = (unsigned)__cvta_generic_to_shared(hS);

    const int tid  = threadIdx.x;
    const int lane = tid & 31;
    const int ks   = tid >> 5;    // warp id = k-slice (0..7), 128 k each
    const int g    = lane >> 2;
    const int tig  = lane & 3;

    const int d0 = blockIdx.x * 8;
    const int fidx = ((tid + blockIdx.x) & (NCTA - 1)) * 8;  // rotated flag slot

    // ---- preload this warp's U fragments into registers (one-time) ----
    unsigned breg[8][4][2];
#pragma unroll
    for (int kk = 0; kk < 8; kk++) {
#pragma unroll
        for (int ng = 0; ng < 4; ng++) {
            const int col = ng * H_ + d0 + g;
            const int k0  = ks * 128 + kk * 16 + 2 * tig;
            breg[kk][ng][0] = pack_bf16(U[(size_t)(k0    ) * G4 + col],
                                        U[(size_t)(k0 + 1) * G4 + col]);
            breg[kk][ng][1] = pack_bf16(U[(size_t)(k0 + 8) * G4 + col],
                                        U[(size_t)(k0 + 9) * G4 + col]);
        }
    }

    const int eb = tid >> 3;     // gate-phase batch
    const int ed = tid & 7;      // gate-phase local dim
    float c_reg = 0.0f;

    // prefetch xz + residual x for t = 0 (stream order covers xw_gemm writes)
    float zin[4];
#pragma unroll
    for (int gate = 0; gate < 4; gate++)
        zin[gate] = __ldcg(&g_xz[((size_t)eb * T_ + 0) * G4 + gate * H_ + d0 + ed]);
    size_t xi = ((size_t)eb * T_ + 0) * H_ + d0 + ed;
    float xres = __ldcg(&x[xi]);

    for (int t = 0; t < T_; t++) {
        const unsigned stamp = (unsigned)(t + 1);
        const __nv_bfloat16* hprev = g_hbf[t & 1];
        __nv_bfloat16*       hcur  = g_hbf[(t + 1) & 1];

        // ---- per-warp k-slice staging: warp ks loads h[:, ks*128 .. +128) ----
#pragma unroll
        for (int i = 0; i < 16; i++) {
            int q = i * 32 + lane;        // 0..511 chunk of warp's 8KB slice
            int r = q >> 4;               // batch row 0..31
            int c = q & 15;               // 16B chunk within 256B row-slice
            cp16(hS_base + (unsigned)(r * HS_STRIDE + ks * 128 + c * 8) * 2,
                 hprev + r * H_ + ks * 128 + c * 8);
        }
        asm volatile("cp.async.commit_group;");
        asm volatile("cp.async.wait_group 0;" ::: "memory");
        // no __syncthreads: each warp consumes only its own slice

        // ---- z partials: per warp [32 x 32] over its 128-k slice ----
        float acc[2][4][4];
#pragma unroll
        for (int mi = 0; mi < 2; mi++)
#pragma unroll
            for (int ng = 0; ng < 4; ng++)
#pragma unroll
                for (int q = 0; q < 4; q++) acc[mi][ng][q] = 0.0f;

#pragma unroll
        for (int kk = 0; kk < 8; kk++) {
            const int kcol = ks * 128 + kk * 16 + 2 * tig;
#pragma unroll
            for (int mi = 0; mi < 2; mi++) {
                const __nv_bfloat16* r0 = hS + (mi * 16 + g) * HS_STRIDE;
                const __nv_bfloat16* r1 = hS + (mi * 16 + g + 8) * HS_STRIDE;
                unsigned a0 = *(const unsigned*)(r0 + kcol);
                unsigned a1 = *(const unsigned*)(r1 + kcol);
                unsigned a2 = *(const unsigned*)(r0 + kcol + 8);
                unsigned a3 = *(const unsigned*)(r1 + kcol + 8);
#pragma unroll
                for (int ng = 0; ng < 4; ng++)
                    mma_bf16(acc[mi][ng], a0, a1, a2, a3,
                             breg[kk][ng][0], breg[kk][ng][1]);
            }
        }

        // ---- write k-partials ----
#pragma unroll
        for (int mi = 0; mi < 2; mi++) {
#pragma unroll
            for (int ng = 0; ng < 4; ng++) {
                const int col = ng * 8 + 2 * tig;
                float* r0 = redS + (ks * 32 + mi * 16 + g)     * RED_STRIDE + col;
                float* r1 = redS + (ks * 32 + mi * 16 + g + 8) * RED_STRIDE + col;
                *(float2*)r0 = make_float2(acc[mi][ng][0], acc[mi][ng][1]);
                *(float2*)r1 = make_float2(acc[mi][ng][2], acc[mi][ng][3]);
            }
        }
        __syncthreads();

        // ---- gates + state update ----
        const float* rb = redS + eb * RED_STRIDE + ed;
        float z[4];
#pragma unroll
        for (int gate = 0; gate < 4; gate++) {
            const float* p = rb + gate * 8;
            float s = zin[gate];
#pragma unroll
            for (int q = 0; q < 8; q++) s += p[q * 32 * RED_STRIDE];
            z[gate] = s;
        }
        float ig = sigf(z[0]);
        float fg = sigf(z[1]);
        float gg = tanh_fast(z[2]);
        float og = sigf(z[3]);

        c_reg = fg * c_reg + ig * gg;
        float hn = og * tanh_fast(c_reg);
        hcur[eb * H_ + d0 + ed] = __float2bfloat16(hn);

        // ---- publish h ----
        __syncthreads();                       // CTA's h chunk complete
        if (tid == 0) st_rel(&g_flags[blockIdx.x * 8], stamp);

        // ---- off-critical-path work while peers arrive ----
        out[xi] = tanh_fast(hn + xres);
        if (t + 1 < T_) {
#pragma unroll
            for (int gate = 0; gate < 4; gate++)
                zin[gate] = __ldcg(&g_xz[((size_t)eb * T_ + t + 1) * G4 + gate * H_ + d0 + ed]);
            xi = ((size_t)eb * T_ + t + 1) * H_ + d0 + ed;
            xres = __ldcg(&x[xi]);
        }

        // ---- one-hop flat barrier: all CTAs poll all flags ----
        if (tid < NCTA) {
            while (ld_acq(&g_flags[fidx]) < stamp) { }
        }
        __syncthreads();
    }
}

// ---------------------------------------------------------------------------
extern "C" void kernel_launch(void* const* d_in, const int* in_sizes, int n_in,
                              void* d_out, int out_size) {
    const float* x    = (const float*)d_in[0];
    const float* W    = (const float*)d_in[1];
    const float* U    = (const float*)d_in[2];
    const float* bias = (const float*)d_in[3];
    float* out        = (float*)d_out;

    cudaFuncSetAttribute(lstm_persistent,
                         cudaFuncAttributeMaxDynamicSharedMemorySize, SMEM_BYTES);

    dim3 grid_gemm(G4 / 64, (B_ * T_) / 64);   // (64, 256)
    xw_gemm<<<grid_gemm, 256>>>(x, W, bias);

    lstm_persistent<<<NCTA, NTHREADS, SMEM_BYTES>>>(U, x, out);
}